// round 5
// baseline (speedup 1.0000x reference)
#include <cuda_runtime.h>

#define NN 50000
#define NE 600000
#define HID 128
#define TILE_N 64
#define KCH 32          // K-chunk for the GEMM

typedef unsigned long long u64;

// Scratch (static device globals — no runtime allocation).
__device__ __align__(256) float g_q[(size_t)NN * HID];
__device__ __align__(256) float g_k[(size_t)NN * HID];
__device__ __align__(256) float g_v[(size_t)NN * HID];
__device__ __align__(256) float g_WT[3 * HID * HID];  // g_WT[m][d][o] = W_m[o][d]
__device__ __align__(256) int   g_src[NE];
__device__ __align__(256) int   g_dst[NE];
__device__ __align__(256) int   g_count[NN];     // per-dst degree
__device__ __align__(256) int   g_start[NN + 1]; // CSR offsets
__device__ __align__(256) int   g_cursor[NN];    // permute cursors
__device__ __align__(256) int   g_eperm[NE];     // edge ids sorted by dst
__device__ __align__(256) int   g_src_s[NE];     // src pre-gathered in sorted order
__device__ int g_is_i32;

// ---------------------------------------------------------------------------
// f32x2 packed-FMA helpers (Blackwell FFMA2 — PTX-only, exact fp32).
// ---------------------------------------------------------------------------
__device__ __forceinline__ u64 pack2(float lo, float hi) {
    u64 r; asm("mov.b64 %0, {%1, %2};" : "=l"(r) : "f"(lo), "f"(hi)); return r;
}
__device__ __forceinline__ void fma2(u64& acc, u64 a, u64 b) {
    asm("fma.rn.f32x2 %0, %1, %2, %0;" : "+l"(acc) : "l"(a), "l"(b));
}

// ---------------------------------------------------------------------------
// Kernel Z: zero counters + dtype flag (must precede detect/hist).
// ---------------------------------------------------------------------------
__global__ void zero_counts() {
    int t = blockIdx.x * blockDim.x + threadIdx.x;
    if (t == 0) g_is_i32 = 0;
    for (int i = t; i < NN; i += blockDim.x * gridDim.x) g_count[i] = 0;
}

// ---------------------------------------------------------------------------
// Kernel A: dtype detection (int32 vs int64 edge_index). int64 indices
// < 2^31 have every odd 32-bit word zero.
// ---------------------------------------------------------------------------
__global__ void detect_idx(const unsigned int* __restrict__ ei_words) {
    int t = blockIdx.x * blockDim.x + threadIdx.x;
    unsigned int acc = 0;
    for (int i = t; i < NE; i += blockDim.x * gridDim.x)
        acc |= ei_words[2 * i + 1];
    if (acc) atomicOr(&g_is_i32, 1);
}

// ---------------------------------------------------------------------------
// Kernel B: decode edge_index into g_src/g_dst AND histogram dst degrees.
// ---------------------------------------------------------------------------
__global__ void convert_idx(const unsigned int* __restrict__ ei_words) {
    int t = blockIdx.x * blockDim.x + threadIdx.x;
    int i32 = g_is_i32;
    for (int e = t; e < NE; e += blockDim.x * gridDim.x) {
        int s, d;
        if (i32) {
            s = (int)ei_words[e];
            d = (int)ei_words[NE + e];
        } else {
            s = (int)ei_words[2 * (size_t)e];
            d = (int)ei_words[2 * ((size_t)NE + e)];
        }
        g_src[e] = s;
        g_dst[e] = d;
        atomicAdd(&g_count[d], 1);
    }
}

// ---------------------------------------------------------------------------
// Kernel C: single-block prefix scan over 50k degrees -> g_start / g_cursor.
// ---------------------------------------------------------------------------
__global__ void scan_kernel() {
    __shared__ int ps[1024];
    int tid = threadIdx.x;
    const int PER = (NN + 1023) / 1024;   // 49
    int base = tid * PER;
    int sum = 0;
    for (int i = 0; i < PER; i++) {
        int idx = base + i;
        if (idx < NN) sum += g_count[idx];
    }
    ps[tid] = sum;
    __syncthreads();
    for (int d = 1; d < 1024; d <<= 1) {
        int v = (tid >= d) ? ps[tid - d] : 0;
        __syncthreads();
        ps[tid] += v;
        __syncthreads();
    }
    int run = ps[tid] - sum;   // exclusive prefix
    for (int i = 0; i < PER; i++) {
        int idx = base + i;
        if (idx < NN) {
            g_start[idx] = run;
            g_cursor[idx] = run;
            run += g_count[idx];
        }
    }
    if (tid == 1023) g_start[NN] = run;
}

// ---------------------------------------------------------------------------
// Kernel D: permute edge ids into dst-sorted order (atomic cursors; order
// within a segment is race-dependent but only affects fp summation order).
// ---------------------------------------------------------------------------
__global__ void permute_idx() {
    int t = blockIdx.x * blockDim.x + threadIdx.x;
    for (int e = t; e < NE; e += blockDim.x * gridDim.x) {
        int d = g_dst[e];
        int pos = atomicAdd(&g_cursor[d], 1);
        g_eperm[pos] = e;
        g_src_s[pos] = g_src[e];
    }
}

// ---------------------------------------------------------------------------
// Kernel 0: transpose the three 128x128 weight matrices (tiny).
// ---------------------------------------------------------------------------
__global__ void transpose_w(const float* __restrict__ Wq,
                            const float* __restrict__ Wk,
                            const float* __restrict__ Wv) {
    int t = blockIdx.x * blockDim.x + threadIdx.x;
    int total = 3 * HID * HID;
    for (int idx = t; idx < total; idx += blockDim.x * gridDim.x) {
        int m = idx / (HID * HID);
        int r = idx - m * (HID * HID);
        int o = r >> 7;
        int d = r & 127;
        const float* W = (m == 0) ? Wq : (m == 1) ? Wk : Wv;
        g_WT[m * HID * HID + d * HID + o] = W[o * HID + d];
    }
}

// ---------------------------------------------------------------------------
// Kernel 1: QKV GEMM with packed f32x2 FMAs. Tile 64 nodes x 128 outs,
// K-chunks of 32 via static smem with register-staged prefetch. Warp w owns
// nodes 8w..8w+7, lane l owns outputs 4l..4l+3. Accumulators are b64 pairs
// (c.x,c.y)/(c.z,c.w); W pairs reinterpret directly from the float4 smem
// load; x scalars broadcast-packed (alu-pipe MOV, off the fma pipe).
// ---------------------------------------------------------------------------
__global__ __launch_bounds__(256) void qkv_gemm(const float* __restrict__ x) {
    __shared__ float wt[KCH][HID];      // transposed W chunk [d][o]
    __shared__ float xs[TILE_N][KCH];   // x tile chunk [n][d]

    int m = blockIdx.y;
    const float* wtg = &g_WT[m * HID * HID];
    float* out = (m == 0) ? g_q : (m == 1) ? g_k : g_v;

    int node0 = blockIdx.x * TILE_N;
    int tid = threadIdx.x;
    int w = tid >> 5;
    int l = tid & 31;

    const float4* xg4 = (const float4*)x;

    float4 wreg[4];
    float4 xreg[2];
    int xn0 = tid >> 3,        xc0 = tid & 7;
    int xn1 = (tid + 256) >> 3, xc1 = (tid + 256) & 7;
    int gn0 = node0 + xn0, gn1 = node0 + xn1;

    auto load_chunk = [&](int k0) {
        const float4* srcw = (const float4*)&wtg[(size_t)k0 * HID];
#pragma unroll
        for (int i = 0; i < 4; i++) wreg[i] = srcw[tid + i * 256];
        xreg[0] = (gn0 < NN) ? xg4[(size_t)gn0 * 32 + (k0 >> 2) + xc0]
                             : make_float4(0.f, 0.f, 0.f, 0.f);
        xreg[1] = (gn1 < NN) ? xg4[(size_t)gn1 * 32 + (k0 >> 2) + xc1]
                             : make_float4(0.f, 0.f, 0.f, 0.f);
    };
    auto store_chunk = [&]() {
        float4* wt4 = (float4*)&wt[0][0];
        float4* xs4 = (float4*)&xs[0][0];
#pragma unroll
        for (int i = 0; i < 4; i++) wt4[tid + i * 256] = wreg[i];
        xs4[tid] = xreg[0];
        xs4[tid + 256] = xreg[1];
    };

    u64 cxy[8], czw[8];
#pragma unroll
    for (int n = 0; n < 8; n++) { cxy[n] = 0ull; czw[n] = 0ull; }

    load_chunk(0);
    store_chunk();
    __syncthreads();

#pragma unroll
    for (int kk = 0; kk < HID / KCH; kk++) {
        if (kk + 1 < HID / KCH)
            load_chunk((kk + 1) * KCH);

#pragma unroll
        for (int d4 = 0; d4 < KCH / 4; d4++) {
            int d = d4 * 4;
            // 128-bit smem loads, viewed as (xy,zw) b64 pairs
            ulonglong2 w0 = *(ulonglong2*)&wt[d + 0][4 * l];
            ulonglong2 w1 = *(ulonglong2*)&wt[d + 1][4 * l];
            ulonglong2 w2 = *(ulonglong2*)&wt[d + 2][4 * l];
            ulonglong2 w3 = *(ulonglong2*)&wt[d + 3][4 * l];
#pragma unroll
            for (int n = 0; n < 8; n++) {
                float4 xv = *(float4*)&xs[8 * w + n][d];
                u64 xb0 = pack2(xv.x, xv.x);
                u64 xb1 = pack2(xv.y, xv.y);
                u64 xb2 = pack2(xv.z, xv.z);
                u64 xb3 = pack2(xv.w, xv.w);
                fma2(cxy[n], xb0, w0.x); fma2(czw[n], xb0, w0.y);
                fma2(cxy[n], xb1, w1.x); fma2(czw[n], xb1, w1.y);
                fma2(cxy[n], xb2, w2.x); fma2(czw[n], xb2, w2.y);
                fma2(cxy[n], xb3, w3.x); fma2(czw[n], xb3, w3.y);
            }
        }
        __syncthreads();
        if (kk + 1 < HID / KCH) {
            store_chunk();
            __syncthreads();
        }
    }

#pragma unroll
    for (int n = 0; n < 8; n++) {
        int gn = node0 + 8 * w + n;
        if (gn < NN) {
            ulonglong2 o2;
            o2.x = cxy[n];
            o2.y = czw[n];
            *(ulonglong2*)&out[(size_t)gn * HID + 4 * l] = o2;
        }
    }
}

// ---------------------------------------------------------------------------
// Kernel 2: dst-sorted edge aggregation. One warp per dst node: q loaded
// once, per-edge k/v/w gathers, quad shfl-reduce for per-head alpha,
// register accumulation, single STG.128 per lane. No atomics, no memset.
// ---------------------------------------------------------------------------
__global__ __launch_bounds__(256) void edge_agg(
    const float* __restrict__ w_ij,
    const float* __restrict__ cutoff,
    float* __restrict__ out) {

    int node = (blockIdx.x * blockDim.x + threadIdx.x) >> 5;
    int l = threadIdx.x & 31;
    if (node >= NN) return;

    int s = g_start[node];
    int e_end = g_start[node + 1];

    float4 q = *(const float4*)&g_q[(size_t)node * HID + 4 * l];
    float4 acc = make_float4(0.f, 0.f, 0.f, 0.f);

    for (int p = s; p < e_end; p++) {
        int e   = g_eperm[p];
        int src = g_src_s[p];

        float4 k  = *(const float4*)&g_k[(size_t)src * HID + 4 * l];
        float4 v  = *(const float4*)&g_v[(size_t)src * HID + 4 * l];
        float4 wv = *(const float4*)&w_ij[(size_t)e * HID + 4 * l];

        float pp = q.x * wv.x * k.x + q.y * wv.y * k.y +
                   q.z * wv.z * k.z + q.w * wv.w * k.w;
        pp += __shfl_xor_sync(0xffffffffu, pp, 1);
        pp += __shfl_xor_sync(0xffffffffu, pp, 2);

        float alpha = pp * 0.25f * __ldg(&cutoff[e]);   // 1/sqrt(16)

        acc.x = fmaf(alpha, v.x, acc.x);
        acc.y = fmaf(alpha, v.y, acc.y);
        acc.z = fmaf(alpha, v.z, acc.z);
        acc.w = fmaf(alpha, v.w, acc.w);
    }

    *(float4*)&out[(size_t)node * HID + 4 * l] = acc;
}

// ---------------------------------------------------------------------------
extern "C" void kernel_launch(void* const* d_in, const int* in_sizes, int n_in,
                              void* d_out, int out_size) {
    const float* x      = (const float*)d_in[0];
    const float* w_ij   = (const float*)d_in[1];
    const unsigned int* ei = (const unsigned int*)d_in[2];
    const float* cutoff = (const float*)d_in[3];
    const float* Wq     = (const float*)d_in[4];
    const float* Wk     = (const float*)d_in[5];
    const float* Wv     = (const float*)d_in[6];
    float* out = (float*)d_out;

    zero_counts<<<64, 256>>>();
    detect_idx<<<148, 256>>>(ei);
    convert_idx<<<148, 256>>>(ei);
    scan_kernel<<<1, 1024>>>();
    permute_idx<<<148, 256>>>();

    transpose_w<<<48, 256>>>(Wq, Wk, Wv);

    dim3 grid((NN + TILE_N - 1) / TILE_N, 3);
    qkv_gemm<<<grid, 256>>>(x);

    int agg_blocks = (NN * 32 + 255) / 256;   // warp per node
    edge_agg<<<agg_blocks, 256>>>(w_ij, cutoff, out);
}

// round 6
// speedup vs baseline: 1.2678x; 1.2678x over previous
#include <cuda_runtime.h>

#define NN 50000
#define NE 600000
#define HID 128
#define TILE_N 64
#define KCH 32          // K-chunk for the GEMM
#define SCAN_B 1024
#define NBLK ((NN + SCAN_B - 1) / SCAN_B)   // 49 scan blocks

typedef unsigned long long u64;

// Scratch (static device globals — no runtime allocation).
__device__ __align__(256) float g_q[(size_t)NN * HID];
__device__ __align__(256) float g_k[(size_t)NN * HID];
__device__ __align__(256) float g_v[(size_t)NN * HID];
__device__ __align__(256) float g_WT[3 * HID * HID];  // g_WT[m][d][o] = W_m[o][d]
__device__ __align__(256) int   g_src[NE];
__device__ __align__(256) int   g_dst[NE];
__device__ __align__(256) int   g_count[NN];     // per-dst degree
__device__ __align__(256) int   g_start[NN + 1]; // CSR offsets
__device__ __align__(256) int   g_cursor[NN];    // permute cursors
__device__ __align__(256) int   g_eperm[NE];     // edge ids sorted by dst
__device__ __align__(256) int   g_src_s[NE];     // src pre-gathered, sorted order
__device__ __align__(256) int   g_bsum[NBLK];    // scan block sums
__device__ __align__(256) int   g_boff[NBLK];    // scan block offsets
__device__ int g_is_i32;

// ---------------------------------------------------------------------------
// f32x2 packed-FMA helpers (Blackwell FFMA2 — PTX-only, exact fp32).
// ---------------------------------------------------------------------------
__device__ __forceinline__ u64 pack2(float lo, float hi) {
    u64 r; asm("mov.b64 %0, {%1, %2};" : "=l"(r) : "f"(lo), "f"(hi)); return r;
}
__device__ __forceinline__ void fma2(u64& acc, u64 a, u64 b) {
    asm("fma.rn.f32x2 %0, %1, %2, %0;" : "+l"(acc) : "l"(a), "l"(b));
}

// ---------------------------------------------------------------------------
// Kernel Z: zero counters + dtype flag.
// ---------------------------------------------------------------------------
__global__ void zero_counts() {
    int t = blockIdx.x * blockDim.x + threadIdx.x;
    if (t == 0) g_is_i32 = 0;
    for (int i = t; i < NN; i += blockDim.x * gridDim.x) g_count[i] = 0;
}

// ---------------------------------------------------------------------------
// Kernel A: dtype detection (int32 vs int64 edge_index). int64 indices
// < 2^31 have every odd 32-bit word zero.
// ---------------------------------------------------------------------------
__global__ void detect_idx(const unsigned int* __restrict__ ei_words) {
    int t = blockIdx.x * blockDim.x + threadIdx.x;
    unsigned int acc = 0;
    for (int i = t; i < NE; i += blockDim.x * gridDim.x)
        acc |= ei_words[2 * i + 1];
    if (acc) atomicOr(&g_is_i32, 1);
}

// ---------------------------------------------------------------------------
// Kernel B: decode edge_index into g_src/g_dst AND histogram dst degrees.
// ---------------------------------------------------------------------------
__global__ void convert_idx(const unsigned int* __restrict__ ei_words) {
    int t = blockIdx.x * blockDim.x + threadIdx.x;
    int i32 = g_is_i32;
    for (int e = t; e < NE; e += blockDim.x * gridDim.x) {
        int s, d;
        if (i32) {
            s = (int)ei_words[e];
            d = (int)ei_words[NE + e];
        } else {
            s = (int)ei_words[2 * (size_t)e];
            d = (int)ei_words[2 * ((size_t)NE + e)];
        }
        g_src[e] = s;
        g_dst[e] = d;
        atomicAdd(&g_count[d], 1);
    }
}

// ---------------------------------------------------------------------------
// Parallel 3-phase scan (replaces the 84us single-block serial scan).
// Phase 1: per-block smem scan; writes local exclusive prefix + block sum.
// ---------------------------------------------------------------------------
__global__ __launch_bounds__(SCAN_B) void scan_phase1() {
    __shared__ int ps[SCAN_B];
    int tid = threadIdx.x;
    int idx = blockIdx.x * SCAN_B + tid;
    int val = (idx < NN) ? g_count[idx] : 0;
    ps[tid] = val;
    __syncthreads();
#pragma unroll
    for (int d = 1; d < SCAN_B; d <<= 1) {
        int v = (tid >= d) ? ps[tid - d] : 0;
        __syncthreads();
        ps[tid] += v;
        __syncthreads();
    }
    if (idx < NN) g_start[idx] = ps[tid] - val;   // local exclusive prefix
    if (tid == SCAN_B - 1) g_bsum[blockIdx.x] = ps[tid];
}

// Phase 2: one warp scans the 49 block sums.
__global__ void scan_phase2() {
    int l = threadIdx.x;             // 64 threads, NBLK=49 <= 64
    int v = (l < NBLK) ? g_bsum[l] : 0;
    int orig = v;
    // inclusive warp-style scan over 64 lanes via smem (tiny)
    __shared__ int s[64];
    s[l] = v;
    __syncthreads();
#pragma unroll
    for (int d = 1; d < 64; d <<= 1) {
        int t = (l >= d) ? s[l - d] : 0;
        __syncthreads();
        s[l] += t;
        __syncthreads();
    }
    if (l < NBLK) g_boff[l] = s[l] - orig;        // exclusive
    if (l == 63) g_start[NN] = s[63];             // total = NE
}

// Phase 3: add block offsets; write cursors.
__global__ __launch_bounds__(SCAN_B) void scan_phase3() {
    int idx = blockIdx.x * SCAN_B + threadIdx.x;
    if (idx < NN) {
        int v = g_start[idx] + g_boff[blockIdx.x];
        g_start[idx] = v;
        g_cursor[idx] = v;
    }
}

// ---------------------------------------------------------------------------
// Kernel D: permute edge ids into dst-sorted order.
// ---------------------------------------------------------------------------
__global__ void permute_idx() {
    int t = blockIdx.x * blockDim.x + threadIdx.x;
    for (int e = t; e < NE; e += blockDim.x * gridDim.x) {
        int d = g_dst[e];
        int pos = atomicAdd(&g_cursor[d], 1);
        g_eperm[pos] = e;
        g_src_s[pos] = g_src[e];
    }
}

// ---------------------------------------------------------------------------
// Kernel 0: transpose the three 128x128 weight matrices (tiny).
// ---------------------------------------------------------------------------
__global__ void transpose_w(const float* __restrict__ Wq,
                            const float* __restrict__ Wk,
                            const float* __restrict__ Wv) {
    int t = blockIdx.x * blockDim.x + threadIdx.x;
    int total = 3 * HID * HID;
    for (int idx = t; idx < total; idx += blockDim.x * gridDim.x) {
        int m = idx / (HID * HID);
        int r = idx - m * (HID * HID);
        int o = r >> 7;
        int d = r & 127;
        const float* W = (m == 0) ? Wq : (m == 1) ? Wk : Wv;
        g_WT[m * HID * HID + d * HID + o] = W[o * HID + d];
    }
}

// ---------------------------------------------------------------------------
// Kernel 1: QKV GEMM with packed f32x2 FMAs (FFMA2). Tile 64 nodes x 128
// outs, K-chunks of 32 via static smem + register-staged prefetch.
// ---------------------------------------------------------------------------
__global__ __launch_bounds__(256) void qkv_gemm(const float* __restrict__ x) {
    __shared__ float wt[KCH][HID];
    __shared__ float xs[TILE_N][KCH];

    int m = blockIdx.y;
    const float* wtg = &g_WT[m * HID * HID];
    float* out = (m == 0) ? g_q : (m == 1) ? g_k : g_v;

    int node0 = blockIdx.x * TILE_N;
    int tid = threadIdx.x;
    int w = tid >> 5;
    int l = tid & 31;

    const float4* xg4 = (const float4*)x;

    float4 wreg[4];
    float4 xreg[2];
    int xn0 = tid >> 3,         xc0 = tid & 7;
    int xn1 = (tid + 256) >> 3, xc1 = (tid + 256) & 7;
    int gn0 = node0 + xn0, gn1 = node0 + xn1;

    auto load_chunk = [&](int k0) {
        const float4* srcw = (const float4*)&wtg[(size_t)k0 * HID];
#pragma unroll
        for (int i = 0; i < 4; i++) wreg[i] = srcw[tid + i * 256];
        xreg[0] = (gn0 < NN) ? xg4[(size_t)gn0 * 32 + (k0 >> 2) + xc0]
                             : make_float4(0.f, 0.f, 0.f, 0.f);
        xreg[1] = (gn1 < NN) ? xg4[(size_t)gn1 * 32 + (k0 >> 2) + xc1]
                             : make_float4(0.f, 0.f, 0.f, 0.f);
    };
    auto store_chunk = [&]() {
        float4* wt4 = (float4*)&wt[0][0];
        float4* xs4 = (float4*)&xs[0][0];
#pragma unroll
        for (int i = 0; i < 4; i++) wt4[tid + i * 256] = wreg[i];
        xs4[tid] = xreg[0];
        xs4[tid + 256] = xreg[1];
    };

    u64 cxy[8], czw[8];
#pragma unroll
    for (int n = 0; n < 8; n++) { cxy[n] = 0ull; czw[n] = 0ull; }

    load_chunk(0);
    store_chunk();
    __syncthreads();

#pragma unroll
    for (int kk = 0; kk < HID / KCH; kk++) {
        if (kk + 1 < HID / KCH)
            load_chunk((kk + 1) * KCH);

#pragma unroll
        for (int d4 = 0; d4 < KCH / 4; d4++) {
            int d = d4 * 4;
            ulonglong2 w0 = *(ulonglong2*)&wt[d + 0][4 * l];
            ulonglong2 w1 = *(ulonglong2*)&wt[d + 1][4 * l];
            ulonglong2 w2 = *(ulonglong2*)&wt[d + 2][4 * l];
            ulonglong2 w3 = *(ulonglong2*)&wt[d + 3][4 * l];
#pragma unroll
            for (int n = 0; n < 8; n++) {
                float4 xv = *(float4*)&xs[8 * w + n][d];
                u64 xb0 = pack2(xv.x, xv.x);
                u64 xb1 = pack2(xv.y, xv.y);
                u64 xb2 = pack2(xv.z, xv.z);
                u64 xb3 = pack2(xv.w, xv.w);
                fma2(cxy[n], xb0, w0.x); fma2(czw[n], xb0, w0.y);
                fma2(cxy[n], xb1, w1.x); fma2(czw[n], xb1, w1.y);
                fma2(cxy[n], xb2, w2.x); fma2(czw[n], xb2, w2.y);
                fma2(cxy[n], xb3, w3.x); fma2(czw[n], xb3, w3.y);
            }
        }
        __syncthreads();
        if (kk + 1 < HID / KCH) {
            store_chunk();
            __syncthreads();
        }
    }

#pragma unroll
    for (int n = 0; n < 8; n++) {
        int gn = node0 + 8 * w + n;
        if (gn < NN) {
            ulonglong2 o2;
            o2.x = cxy[n];
            o2.y = czw[n];
            *(ulonglong2*)&out[(size_t)gn * HID + 4 * l] = o2;
        }
    }
}

// ---------------------------------------------------------------------------
// Kernel 2: dst-sorted edge aggregation. One warp per dst node: q loaded
// once, per-edge k/v/w gathers, quad shfl-reduce -> per-head alpha, register
// accumulation, single STG.128 per lane. No atomics, no out memset.
// ---------------------------------------------------------------------------
__global__ __launch_bounds__(256) void edge_agg(
    const float* __restrict__ w_ij,
    const float* __restrict__ cutoff,
    float* __restrict__ out) {

    int node = (blockIdx.x * blockDim.x + threadIdx.x) >> 5;
    int l = threadIdx.x & 31;
    if (node >= NN) return;

    int s = g_start[node];
    int e_end = g_start[node + 1];

    float4 q = *(const float4*)&g_q[(size_t)node * HID + 4 * l];
    float4 acc = make_float4(0.f, 0.f, 0.f, 0.f);

    for (int p = s; p < e_end; p++) {
        int e   = g_eperm[p];
        int src = g_src_s[p];

        float4 k  = *(const float4*)&g_k[(size_t)src * HID + 4 * l];
        float4 v  = *(const float4*)&g_v[(size_t)src * HID + 4 * l];
        float4 wv = *(const float4*)&w_ij[(size_t)e * HID + 4 * l];

        float pp = q.x * wv.x * k.x + q.y * wv.y * k.y +
                   q.z * wv.z * k.z + q.w * wv.w * k.w;
        pp += __shfl_xor_sync(0xffffffffu, pp, 1);
        pp += __shfl_xor_sync(0xffffffffu, pp, 2);

        float alpha = pp * 0.25f * __ldg(&cutoff[e]);   // 1/sqrt(16)

        acc.x = fmaf(alpha, v.x, acc.x);
        acc.y = fmaf(alpha, v.y, acc.y);
        acc.z = fmaf(alpha, v.z, acc.z);
        acc.w = fmaf(alpha, v.w, acc.w);
    }

    *(float4*)&out[(size_t)node * HID + 4 * l] = acc;
}

// ---------------------------------------------------------------------------
extern "C" void kernel_launch(void* const* d_in, const int* in_sizes, int n_in,
                              void* d_out, int out_size) {
    const float* x      = (const float*)d_in[0];
    const float* w_ij   = (const float*)d_in[1];
    const unsigned int* ei = (const unsigned int*)d_in[2];
    const float* cutoff = (const float*)d_in[3];
    const float* Wq     = (const float*)d_in[4];
    const float* Wk     = (const float*)d_in[5];
    const float* Wv     = (const float*)d_in[6];
    float* out = (float*)d_out;

    zero_counts<<<64, 256>>>();
    detect_idx<<<148, 256>>>(ei);
    convert_idx<<<148, 256>>>(ei);
    scan_phase1<<<NBLK, SCAN_B>>>();
    scan_phase2<<<1, 64>>>();
    scan_phase3<<<NBLK, SCAN_B>>>();
    permute_idx<<<148, 256>>>();

    transpose_w<<<48, 256>>>(Wq, Wk, Wv);

    dim3 grid((NN + TILE_N - 1) / TILE_N, 3);
    qkv_gemm<<<grid, 256>>>(x);

    int agg_blocks = (NN * 32 + 255) / 256;   // warp per node
    edge_agg<<<agg_blocks, 256>>>(w_ij, cutoff, out);
}

// round 7
// speedup vs baseline: 1.3284x; 1.0478x over previous
#include <cuda_runtime.h>

#define NN 50000
#define NE 600000
#define HID 128
#define TILE_N 64
#define KCH 32          // K-chunk for the GEMM
#define SCAN_B 1024
#define NBLK ((NN + SCAN_B - 1) / SCAN_B)   // 49 scan blocks

typedef unsigned long long u64;

// Scratch (static device globals — no runtime allocation).
__device__ __align__(256) float g_q[(size_t)NN * HID];
__device__ __align__(256) float g_k[(size_t)NN * HID];
__device__ __align__(256) float g_v[(size_t)NN * HID];
__device__ __align__(256) float g_WT[3 * HID * HID];  // g_WT[m][d][o] = W_m[o][d]
__device__ __align__(256) int   g_src[NE];
__device__ __align__(256) int   g_dst[NE];
__device__ __align__(256) int   g_count[NN];     // per-dst degree
__device__ __align__(256) int   g_start[NN + 1]; // CSR offsets
__device__ __align__(256) int   g_cursor[NN];    // permute cursors
__device__ __align__(256) int2  g_es[NE];        // (edge id, src) sorted by dst
__device__ __align__(256) int   g_bsum[NBLK];
__device__ __align__(256) int   g_boff[NBLK];
__device__ int g_is_i32;

// ---------------------------------------------------------------------------
// f32x2 packed-FMA helpers (FFMA2 — PTX-only, exact fp32).
// ---------------------------------------------------------------------------
__device__ __forceinline__ u64 pack2(float lo, float hi) {
    u64 r; asm("mov.b64 %0, {%1, %2};" : "=l"(r) : "f"(lo), "f"(hi)); return r;
}
__device__ __forceinline__ void fma2(u64& acc, u64 a, u64 b) {
    asm("fma.rn.f32x2 %0, %1, %2, %0;" : "+l"(acc) : "l"(a), "l"(b));
}

// ---------------------------------------------------------------------------
// Kernel Z: zero counters + dtype flag + detection in one pass.
// int64 indices < 2^31 have every odd 32-bit word zero.
// ---------------------------------------------------------------------------
__global__ void zero_and_detect(const unsigned int* __restrict__ ei_words) {
    int t = blockIdx.x * blockDim.x + threadIdx.x;
    if (t == 0) g_is_i32 = 0;
    for (int i = t; i < NN; i += blockDim.x * gridDim.x) g_count[i] = 0;
    unsigned int acc = 0;
    for (int i = t; i < NE; i += blockDim.x * gridDim.x)
        acc |= ei_words[2 * i + 1];
    if (acc) atomicOr(&g_is_i32, 1);
}

// ---------------------------------------------------------------------------
// Kernel B: decode edge_index into g_src/g_dst AND histogram dst degrees.
// (g_is_i32 written by prior kernel; safe: separate launch.)
// ---------------------------------------------------------------------------
__global__ void convert_idx(const unsigned int* __restrict__ ei_words) {
    int t = blockIdx.x * blockDim.x + threadIdx.x;
    int i32 = g_is_i32;
    for (int e = t; e < NE; e += blockDim.x * gridDim.x) {
        int s, d;
        if (i32) {
            s = (int)ei_words[e];
            d = (int)ei_words[NE + e];
        } else {
            s = (int)ei_words[2 * (size_t)e];
            d = (int)ei_words[2 * ((size_t)NE + e)];
        }
        g_src[e] = s;
        g_dst[e] = d;
        atomicAdd(&g_count[d], 1);
    }
}

// ---------------------------------------------------------------------------
// 3-phase parallel scan.
// ---------------------------------------------------------------------------
__global__ __launch_bounds__(SCAN_B) void scan_phase1() {
    __shared__ int ps[SCAN_B];
    int tid = threadIdx.x;
    int idx = blockIdx.x * SCAN_B + tid;
    int val = (idx < NN) ? g_count[idx] : 0;
    ps[tid] = val;
    __syncthreads();
#pragma unroll
    for (int d = 1; d < SCAN_B; d <<= 1) {
        int v = (tid >= d) ? ps[tid - d] : 0;
        __syncthreads();
        ps[tid] += v;
        __syncthreads();
    }
    if (idx < NN) g_start[idx] = ps[tid] - val;
    if (tid == SCAN_B - 1) g_bsum[blockIdx.x] = ps[tid];
}

__global__ void scan_phase2() {
    int l = threadIdx.x;             // 64 threads, NBLK=49 <= 64
    int v = (l < NBLK) ? g_bsum[l] : 0;
    int orig = v;
    __shared__ int s[64];
    s[l] = v;
    __syncthreads();
#pragma unroll
    for (int d = 1; d < 64; d <<= 1) {
        int t = (l >= d) ? s[l - d] : 0;
        __syncthreads();
        s[l] += t;
        __syncthreads();
    }
    if (l < NBLK) g_boff[l] = s[l] - orig;
    if (l == 63) g_start[NN] = s[63];
}

__global__ __launch_bounds__(SCAN_B) void scan_phase3() {
    int idx = blockIdx.x * SCAN_B + threadIdx.x;
    if (idx < NN) {
        int v = g_start[idx] + g_boff[blockIdx.x];
        g_start[idx] = v;
        g_cursor[idx] = v;
    }
}

// ---------------------------------------------------------------------------
// Kernel D: permute (edge id, src) pairs into dst-sorted order.
// ---------------------------------------------------------------------------
__global__ void permute_idx() {
    int t = blockIdx.x * blockDim.x + threadIdx.x;
    for (int e = t; e < NE; e += blockDim.x * gridDim.x) {
        int d = g_dst[e];
        int pos = atomicAdd(&g_cursor[d], 1);
        g_es[pos] = make_int2(e, g_src[e]);
    }
}

// ---------------------------------------------------------------------------
// Kernel 0: transpose the three 128x128 weight matrices (tiny).
// ---------------------------------------------------------------------------
__global__ void transpose_w(const float* __restrict__ Wq,
                            const float* __restrict__ Wk,
                            const float* __restrict__ Wv) {
    int t = blockIdx.x * blockDim.x + threadIdx.x;
    int total = 3 * HID * HID;
    for (int idx = t; idx < total; idx += blockDim.x * gridDim.x) {
        int m = idx / (HID * HID);
        int r = idx - m * (HID * HID);
        int o = r >> 7;
        int d = r & 127;
        const float* W = (m == 0) ? Wq : (m == 1) ? Wk : Wv;
        g_WT[m * HID * HID + d * HID + o] = W[o * HID + d];
    }
}

// ---------------------------------------------------------------------------
// Kernel 1: QKV GEMM with packed f32x2 FMAs (FFMA2).
// ---------------------------------------------------------------------------
__global__ __launch_bounds__(256) void qkv_gemm(const float* __restrict__ x) {
    __shared__ float wt[KCH][HID];
    __shared__ float xs[TILE_N][KCH];

    int m = blockIdx.y;
    const float* wtg = &g_WT[m * HID * HID];
    float* out = (m == 0) ? g_q : (m == 1) ? g_k : g_v;

    int node0 = blockIdx.x * TILE_N;
    int tid = threadIdx.x;
    int w = tid >> 5;
    int l = tid & 31;

    const float4* xg4 = (const float4*)x;

    float4 wreg[4];
    float4 xreg[2];
    int xn0 = tid >> 3,         xc0 = tid & 7;
    int xn1 = (tid + 256) >> 3, xc1 = (tid + 256) & 7;
    int gn0 = node0 + xn0, gn1 = node0 + xn1;

    auto load_chunk = [&](int k0) {
        const float4* srcw = (const float4*)&wtg[(size_t)k0 * HID];
#pragma unroll
        for (int i = 0; i < 4; i++) wreg[i] = srcw[tid + i * 256];
        xreg[0] = (gn0 < NN) ? xg4[(size_t)gn0 * 32 + (k0 >> 2) + xc0]
                             : make_float4(0.f, 0.f, 0.f, 0.f);
        xreg[1] = (gn1 < NN) ? xg4[(size_t)gn1 * 32 + (k0 >> 2) + xc1]
                             : make_float4(0.f, 0.f, 0.f, 0.f);
    };
    auto store_chunk = [&]() {
        float4* wt4 = (float4*)&wt[0][0];
        float4* xs4 = (float4*)&xs[0][0];
#pragma unroll
        for (int i = 0; i < 4; i++) wt4[tid + i * 256] = wreg[i];
        xs4[tid] = xreg[0];
        xs4[tid + 256] = xreg[1];
    };

    u64 cxy[8], czw[8];
#pragma unroll
    for (int n = 0; n < 8; n++) { cxy[n] = 0ull; czw[n] = 0ull; }

    load_chunk(0);
    store_chunk();
    __syncthreads();

#pragma unroll
    for (int kk = 0; kk < HID / KCH; kk++) {
        if (kk + 1 < HID / KCH)
            load_chunk((kk + 1) * KCH);

#pragma unroll
        for (int d4 = 0; d4 < KCH / 4; d4++) {
            int d = d4 * 4;
            ulonglong2 w0 = *(ulonglong2*)&wt[d + 0][4 * l];
            ulonglong2 w1 = *(ulonglong2*)&wt[d + 1][4 * l];
            ulonglong2 w2 = *(ulonglong2*)&wt[d + 2][4 * l];
            ulonglong2 w3 = *(ulonglong2*)&wt[d + 3][4 * l];
#pragma unroll
            for (int n = 0; n < 8; n++) {
                float4 xv = *(float4*)&xs[8 * w + n][d];
                u64 xb0 = pack2(xv.x, xv.x);
                u64 xb1 = pack2(xv.y, xv.y);
                u64 xb2 = pack2(xv.z, xv.z);
                u64 xb3 = pack2(xv.w, xv.w);
                fma2(cxy[n], xb0, w0.x); fma2(czw[n], xb0, w0.y);
                fma2(cxy[n], xb1, w1.x); fma2(czw[n], xb1, w1.y);
                fma2(cxy[n], xb2, w2.x); fma2(czw[n], xb2, w2.y);
                fma2(cxy[n], xb3, w3.x); fma2(czw[n], xb3, w3.y);
            }
        }
        __syncthreads();
        if (kk + 1 < HID / KCH) {
            store_chunk();
            __syncthreads();
        }
    }

#pragma unroll
    for (int n = 0; n < 8; n++) {
        int gn = node0 + 8 * w + n;
        if (gn < NN) {
            ulonglong2 o2;
            o2.x = cxy[n];
            o2.y = czw[n];
            *(ulonglong2*)&out[(size_t)gn * HID + 4 * l] = o2;
        }
    }
}

// ---------------------------------------------------------------------------
// Kernel 2: dst-sorted edge aggregation. One warp per dst node, 2-edge
// software pipeline (6 LDG.128 in flight), streaming loads for w_ij/cutoff
// (__ldcs: evict-first keeps L2 for k/v gathers), streaming store for out.
// ---------------------------------------------------------------------------
__global__ __launch_bounds__(256) void edge_agg(
    const float* __restrict__ w_ij,
    const float* __restrict__ cutoff,
    float* __restrict__ out) {

    int node = (blockIdx.x * blockDim.x + threadIdx.x) >> 5;
    int l = threadIdx.x & 31;
    if (node >= NN) return;

    int p     = g_start[node];
    int e_end = g_start[node + 1];

    float4 q = *(const float4*)&g_q[(size_t)node * HID + 4 * l];
    float4 acc = make_float4(0.f, 0.f, 0.f, 0.f);

    for (; p + 2 <= e_end; p += 2) {
        int2 es0 = g_es[p];
        int2 es1 = g_es[p + 1];

        float4 k0  = *(const float4*)&g_k[(size_t)es0.y * HID + 4 * l];
        float4 k1  = *(const float4*)&g_k[(size_t)es1.y * HID + 4 * l];
        float4 v0  = *(const float4*)&g_v[(size_t)es0.y * HID + 4 * l];
        float4 v1  = *(const float4*)&g_v[(size_t)es1.y * HID + 4 * l];
        float4 w0  = __ldcs((const float4*)&w_ij[(size_t)es0.x * HID + 4 * l]);
        float4 w1  = __ldcs((const float4*)&w_ij[(size_t)es1.x * HID + 4 * l]);
        float  c0  = __ldcs(&cutoff[es0.x]);
        float  c1  = __ldcs(&cutoff[es1.x]);

        float p0 = q.x * w0.x * k0.x + q.y * w0.y * k0.y +
                   q.z * w0.z * k0.z + q.w * w0.w * k0.w;
        float p1 = q.x * w1.x * k1.x + q.y * w1.y * k1.y +
                   q.z * w1.z * k1.z + q.w * w1.w * k1.w;
        p0 += __shfl_xor_sync(0xffffffffu, p0, 1);
        p0 += __shfl_xor_sync(0xffffffffu, p0, 2);
        p1 += __shfl_xor_sync(0xffffffffu, p1, 1);
        p1 += __shfl_xor_sync(0xffffffffu, p1, 2);

        float a0 = p0 * 0.25f * c0;
        float a1 = p1 * 0.25f * c1;

        acc.x = fmaf(a0, v0.x, fmaf(a1, v1.x, acc.x));
        acc.y = fmaf(a0, v0.y, fmaf(a1, v1.y, acc.y));
        acc.z = fmaf(a0, v0.z, fmaf(a1, v1.z, acc.z));
        acc.w = fmaf(a0, v0.w, fmaf(a1, v1.w, acc.w));
    }
    if (p < e_end) {
        int2 es0 = g_es[p];
        float4 k0 = *(const float4*)&g_k[(size_t)es0.y * HID + 4 * l];
        float4 v0 = *(const float4*)&g_v[(size_t)es0.y * HID + 4 * l];
        float4 w0 = __ldcs((const float4*)&w_ij[(size_t)es0.x * HID + 4 * l]);
        float p0 = q.x * w0.x * k0.x + q.y * w0.y * k0.y +
                   q.z * w0.z * k0.z + q.w * w0.w * k0.w;
        p0 += __shfl_xor_sync(0xffffffffu, p0, 1);
        p0 += __shfl_xor_sync(0xffffffffu, p0, 2);
        float a0 = p0 * 0.25f * __ldcs(&cutoff[es0.x]);
        acc.x = fmaf(a0, v0.x, acc.x);
        acc.y = fmaf(a0, v0.y, acc.y);
        acc.z = fmaf(a0, v0.z, acc.z);
        acc.w = fmaf(a0, v0.w, acc.w);
    }

    __stcs((float4*)&out[(size_t)node * HID + 4 * l], acc);
}

// ---------------------------------------------------------------------------
extern "C" void kernel_launch(void* const* d_in, const int* in_sizes, int n_in,
                              void* d_out, int out_size) {
    const float* x      = (const float*)d_in[0];
    const float* w_ij   = (const float*)d_in[1];
    const unsigned int* ei = (const unsigned int*)d_in[2];
    const float* cutoff = (const float*)d_in[3];
    const float* Wq     = (const float*)d_in[4];
    const float* Wk     = (const float*)d_in[5];
    const float* Wv     = (const float*)d_in[6];
    float* out = (float*)d_out;

    // Lazily create side stream + fork/join events on the first call
    // (the correctness run — outside graph capture).
    static cudaStream_t s2 = nullptr;
    static cudaEvent_t evFork = nullptr, evJoin = nullptr;
    static bool use_streams = false;
    if (!s2 && !evFork) {
        bool ok = (cudaStreamCreateWithFlags(&s2, cudaStreamNonBlocking) == cudaSuccess)
               && (cudaEventCreateWithFlags(&evFork, cudaEventDisableTiming) == cudaSuccess)
               && (cudaEventCreateWithFlags(&evJoin, cudaEventDisableTiming) == cudaSuccess);
        use_streams = ok;
    }

    if (use_streams) {
        // Fork: sort chain on s2, GEMM chain on the capturing (default) stream.
        cudaEventRecord(evFork, 0);
        cudaStreamWaitEvent(s2, evFork, 0);

        zero_and_detect<<<148, 256, 0, s2>>>(ei);
        convert_idx<<<148, 256, 0, s2>>>(ei);
        scan_phase1<<<NBLK, SCAN_B, 0, s2>>>();
        scan_phase2<<<1, 64, 0, s2>>>();
        scan_phase3<<<NBLK, SCAN_B, 0, s2>>>();
        permute_idx<<<148, 256, 0, s2>>>();
        cudaEventRecord(evJoin, s2);

        transpose_w<<<48, 256>>>(Wq, Wk, Wv);
        dim3 grid((NN + TILE_N - 1) / TILE_N, 3);
        qkv_gemm<<<grid, 256>>>(x);

        // Join: edge_agg needs both chains.
        cudaStreamWaitEvent(0, evJoin, 0);
    } else {
        zero_and_detect<<<148, 256>>>(ei);
        convert_idx<<<148, 256>>>(ei);
        scan_phase1<<<NBLK, SCAN_B>>>();
        scan_phase2<<<1, 64>>>();
        scan_phase3<<<NBLK, SCAN_B>>>();
        permute_idx<<<148, 256>>>();
        transpose_w<<<48, 256>>>(Wq, Wk, Wv);
        dim3 grid((NN + TILE_N - 1) / TILE_N, 3);
        qkv_gemm<<<grid, 256>>>(x);
    }

    int agg_blocks = (NN * 32 + 255) / 256;   // warp per node
    edge_agg<<<agg_blocks, 256>>>(w_ij, cutoff, out);
}

// round 8
// speedup vs baseline: 1.3793x; 1.0383x over previous
#include <cuda_runtime.h>

#define NN 50000
#define NE 600000
#define HID 128
#define TILE_N 64
#define KCH 32
#define SCAN_B 1024
#define NBLK ((NN + SCAN_B - 1) / SCAN_B)   // 49 scan blocks

typedef unsigned long long u64;

// Scratch (static device globals — no runtime allocation).
__device__ __align__(256) float g_q[(size_t)NN * HID];
__device__ __align__(256) float g_k[(size_t)NN * HID];
__device__ __align__(256) float g_v[(size_t)NN * HID];
__device__ __align__(256) float g_alpha[(size_t)NE * 8];  // per-edge per-head alpha
__device__ __align__(256) float g_WT[3 * HID * HID];
__device__ __align__(256) int   g_src[NE];
__device__ __align__(256) int   g_dst[NE];
__device__ __align__(256) int   g_count[NN];
__device__ __align__(256) int   g_start[NN + 1];
__device__ __align__(256) int   g_cursor[NN];
__device__ __align__(256) int2  g_es[NE];        // (edge id, src) sorted by dst
__device__ __align__(256) int   g_bsum[NBLK];
__device__ __align__(256) int   g_boff[NBLK];
__device__ int g_is_i32;

// ---------------------------------------------------------------------------
// f32x2 packed-FMA helpers (FFMA2 — PTX-only, exact fp32).
// ---------------------------------------------------------------------------
__device__ __forceinline__ u64 pack2(float lo, float hi) {
    u64 r; asm("mov.b64 %0, {%1, %2};" : "=l"(r) : "f"(lo), "f"(hi)); return r;
}
__device__ __forceinline__ void fma2(u64& acc, u64 a, u64 b) {
    asm("fma.rn.f32x2 %0, %1, %2, %0;" : "+l"(acc) : "l"(a), "l"(b));
}

// ---------------------------------------------------------------------------
// Kernel Z: zero counters + dtype flag + detection in one pass.
// ---------------------------------------------------------------------------
__global__ void zero_and_detect(const unsigned int* __restrict__ ei_words) {
    int t = blockIdx.x * blockDim.x + threadIdx.x;
    if (t == 0) g_is_i32 = 0;
    for (int i = t; i < NN; i += blockDim.x * gridDim.x) g_count[i] = 0;
    unsigned int acc = 0;
    for (int i = t; i < NE; i += blockDim.x * gridDim.x)
        acc |= ei_words[2 * i + 1];
    if (acc) atomicOr(&g_is_i32, 1);
}

// ---------------------------------------------------------------------------
// Kernel B: decode edge_index into g_src/g_dst AND histogram dst degrees.
// ---------------------------------------------------------------------------
__global__ void convert_idx(const unsigned int* __restrict__ ei_words) {
    int t = blockIdx.x * blockDim.x + threadIdx.x;
    int i32 = g_is_i32;
    for (int e = t; e < NE; e += blockDim.x * gridDim.x) {
        int s, d;
        if (i32) {
            s = (int)ei_words[e];
            d = (int)ei_words[NE + e];
        } else {
            s = (int)ei_words[2 * (size_t)e];
            d = (int)ei_words[2 * ((size_t)NE + e)];
        }
        g_src[e] = s;
        g_dst[e] = d;
        atomicAdd(&g_count[d], 1);
    }
}

// ---------------------------------------------------------------------------
// 3-phase parallel scan.
// ---------------------------------------------------------------------------
__global__ __launch_bounds__(SCAN_B) void scan_phase1() {
    __shared__ int ps[SCAN_B];
    int tid = threadIdx.x;
    int idx = blockIdx.x * SCAN_B + tid;
    int val = (idx < NN) ? g_count[idx] : 0;
    ps[tid] = val;
    __syncthreads();
#pragma unroll
    for (int d = 1; d < SCAN_B; d <<= 1) {
        int v = (tid >= d) ? ps[tid - d] : 0;
        __syncthreads();
        ps[tid] += v;
        __syncthreads();
    }
    if (idx < NN) g_start[idx] = ps[tid] - val;
    if (tid == SCAN_B - 1) g_bsum[blockIdx.x] = ps[tid];
}

__global__ void scan_phase2() {
    int l = threadIdx.x;             // 64 threads, NBLK=49 <= 64
    int v = (l < NBLK) ? g_bsum[l] : 0;
    int orig = v;
    __shared__ int s[64];
    s[l] = v;
    __syncthreads();
#pragma unroll
    for (int d = 1; d < 64; d <<= 1) {
        int t = (l >= d) ? s[l - d] : 0;
        __syncthreads();
        s[l] += t;
        __syncthreads();
    }
    if (l < NBLK) g_boff[l] = s[l] - orig;
    if (l == 63) g_start[NN] = s[63];
}

__global__ __launch_bounds__(SCAN_B) void scan_phase3() {
    int idx = blockIdx.x * SCAN_B + threadIdx.x;
    if (idx < NN) {
        int v = g_start[idx] + g_boff[blockIdx.x];
        g_start[idx] = v;
        g_cursor[idx] = v;
    }
}

// ---------------------------------------------------------------------------
// Kernel D: permute (edge id, src) pairs into dst-sorted order.
// ---------------------------------------------------------------------------
__global__ void permute_idx() {
    int t = blockIdx.x * blockDim.x + threadIdx.x;
    for (int e = t; e < NE; e += blockDim.x * gridDim.x) {
        int d = g_dst[e];
        int pos = atomicAdd(&g_cursor[d], 1);
        g_es[pos] = make_int2(e, g_src[e]);
    }
}

// ---------------------------------------------------------------------------
// Kernel 0: transpose the three 128x128 weight matrices (tiny).
// ---------------------------------------------------------------------------
__global__ void transpose_w(const float* __restrict__ Wq,
                            const float* __restrict__ Wk,
                            const float* __restrict__ Wv) {
    int t = blockIdx.x * blockDim.x + threadIdx.x;
    int total = 3 * HID * HID;
    for (int idx = t; idx < total; idx += blockDim.x * gridDim.x) {
        int m = idx / (HID * HID);
        int r = idx - m * (HID * HID);
        int o = r >> 7;
        int d = r & 127;
        const float* W = (m == 0) ? Wq : (m == 1) ? Wk : Wv;
        g_WT[m * HID * HID + d * HID + o] = W[o * HID + d];
    }
}

// ---------------------------------------------------------------------------
// Kernel 1: QKV GEMM (FFMA2). m = blockIdx.y + m_base so (q,k) and v can be
// launched separately (v overlaps the alpha kernel on the side stream).
// ---------------------------------------------------------------------------
__global__ __launch_bounds__(256) void qkv_gemm(const float* __restrict__ x,
                                                int m_base) {
    __shared__ float wt[KCH][HID];
    __shared__ float xs[TILE_N][KCH];

    int m = blockIdx.y + m_base;
    const float* wtg = &g_WT[m * HID * HID];
    float* out = (m == 0) ? g_q : (m == 1) ? g_k : g_v;

    int node0 = blockIdx.x * TILE_N;
    int tid = threadIdx.x;
    int w = tid >> 5;
    int l = tid & 31;

    const float4* xg4 = (const float4*)x;

    float4 wreg[4];
    float4 xreg[2];
    int xn0 = tid >> 3,         xc0 = tid & 7;
    int xn1 = (tid + 256) >> 3, xc1 = (tid + 256) & 7;
    int gn0 = node0 + xn0, gn1 = node0 + xn1;

    auto load_chunk = [&](int k0) {
        const float4* srcw = (const float4*)&wtg[(size_t)k0 * HID];
#pragma unroll
        for (int i = 0; i < 4; i++) wreg[i] = srcw[tid + i * 256];
        xreg[0] = (gn0 < NN) ? xg4[(size_t)gn0 * 32 + (k0 >> 2) + xc0]
                             : make_float4(0.f, 0.f, 0.f, 0.f);
        xreg[1] = (gn1 < NN) ? xg4[(size_t)gn1 * 32 + (k0 >> 2) + xc1]
                             : make_float4(0.f, 0.f, 0.f, 0.f);
    };
    auto store_chunk = [&]() {
        float4* wt4 = (float4*)&wt[0][0];
        float4* xs4 = (float4*)&xs[0][0];
#pragma unroll
        for (int i = 0; i < 4; i++) wt4[tid + i * 256] = wreg[i];
        xs4[tid] = xreg[0];
        xs4[tid + 256] = xreg[1];
    };

    u64 cxy[8], czw[8];
#pragma unroll
    for (int n = 0; n < 8; n++) { cxy[n] = 0ull; czw[n] = 0ull; }

    load_chunk(0);
    store_chunk();
    __syncthreads();

#pragma unroll
    for (int kk = 0; kk < HID / KCH; kk++) {
        if (kk + 1 < HID / KCH)
            load_chunk((kk + 1) * KCH);

#pragma unroll
        for (int d4 = 0; d4 < KCH / 4; d4++) {
            int d = d4 * 4;
            ulonglong2 w0 = *(ulonglong2*)&wt[d + 0][4 * l];
            ulonglong2 w1 = *(ulonglong2*)&wt[d + 1][4 * l];
            ulonglong2 w2 = *(ulonglong2*)&wt[d + 2][4 * l];
            ulonglong2 w3 = *(ulonglong2*)&wt[d + 3][4 * l];
#pragma unroll
            for (int n = 0; n < 8; n++) {
                float4 xv = *(float4*)&xs[8 * w + n][d];
                u64 xb0 = pack2(xv.x, xv.x);
                u64 xb1 = pack2(xv.y, xv.y);
                u64 xb2 = pack2(xv.z, xv.z);
                u64 xb3 = pack2(xv.w, xv.w);
                fma2(cxy[n], xb0, w0.x); fma2(czw[n], xb0, w0.y);
                fma2(cxy[n], xb1, w1.x); fma2(czw[n], xb1, w1.y);
                fma2(cxy[n], xb2, w2.x); fma2(czw[n], xb2, w2.y);
                fma2(cxy[n], xb3, w3.x); fma2(czw[n], xb3, w3.y);
            }
        }
        __syncthreads();
        if (kk + 1 < HID / KCH) {
            store_chunk();
            __syncthreads();
        }
    }

#pragma unroll
    for (int n = 0; n < 8; n++) {
        int gn = node0 + 8 * w + n;
        if (gn < NN) {
            ulonglong2 o2;
            o2.x = cxy[n];
            o2.y = czw[n];
            *(ulonglong2*)&out[(size_t)gn * HID + 4 * l] = o2;
        }
    }
}

// ---------------------------------------------------------------------------
// Kernel 2a: alpha in EDGE order — w_ij streamed coalesced (__ldcs), q/k
// gathered from L2. One warp per 2 edges; quad (4 lanes) = 1 head; writes
// alpha[e][h] (32B/edge, includes cutoff and 1/sqrt(16) scale).
// ---------------------------------------------------------------------------
__global__ __launch_bounds__(256) void alpha_kernel(
    const float* __restrict__ w_ij,
    const float* __restrict__ cutoff) {

    int wg = (blockIdx.x * blockDim.x + threadIdx.x) >> 5;
    int l = threadIdx.x & 31;
    int e0 = wg * 2;
    if (e0 >= NE) return;
    int e1 = e0 + 1;   // NE even -> always valid

    int s0 = g_src[e0], d0 = g_dst[e0];
    int s1 = g_src[e1], d1 = g_dst[e1];

    float4 q0 = *(const float4*)&g_q[(size_t)d0 * HID + 4 * l];
    float4 q1 = *(const float4*)&g_q[(size_t)d1 * HID + 4 * l];
    float4 k0 = *(const float4*)&g_k[(size_t)s0 * HID + 4 * l];
    float4 k1 = *(const float4*)&g_k[(size_t)s1 * HID + 4 * l];
    float4 w0 = __ldcs((const float4*)&w_ij[(size_t)e0 * HID + 4 * l]);
    float4 w1 = __ldcs((const float4*)&w_ij[(size_t)e1 * HID + 4 * l]);
    float  c0 = __ldcs(&cutoff[e0]);
    float  c1 = __ldcs(&cutoff[e1]);

    float p0 = q0.x * w0.x * k0.x + q0.y * w0.y * k0.y +
               q0.z * w0.z * k0.z + q0.w * w0.w * k0.w;
    float p1 = q1.x * w1.x * k1.x + q1.y * w1.y * k1.y +
               q1.z * w1.z * k1.z + q1.w * w1.w * k1.w;
    p0 += __shfl_xor_sync(0xffffffffu, p0, 1);
    p0 += __shfl_xor_sync(0xffffffffu, p0, 2);
    p1 += __shfl_xor_sync(0xffffffffu, p1, 1);
    p1 += __shfl_xor_sync(0xffffffffu, p1, 2);

    if ((l & 3) == 0) {
        int h = l >> 2;
        g_alpha[(size_t)e0 * 8 + h] = p0 * 0.25f * c0;
        g_alpha[(size_t)e1 * 8 + h] = p1 * 0.25f * c1;
    }
}

// ---------------------------------------------------------------------------
// Kernel 2b: dst-sorted aggregation. One warp per node; per edge only a
// v-gather (L2-resident, 25.6MB) + a 32B alpha gather. Unroll 4 -> 12+
// loads in flight. No atomics; single streaming STG.128 per lane.
// ---------------------------------------------------------------------------
__global__ __launch_bounds__(256) void edge_agg(float* __restrict__ out) {
    int node = (blockIdx.x * blockDim.x + threadIdx.x) >> 5;
    int l = threadIdx.x & 31;
    if (node >= NN) return;

    int p     = g_start[node];
    int e_end = g_start[node + 1];
    int h = l >> 2;

    float4 acc = make_float4(0.f, 0.f, 0.f, 0.f);

    for (; p + 4 <= e_end; p += 4) {
        int2 es0 = g_es[p];
        int2 es1 = g_es[p + 1];
        int2 es2 = g_es[p + 2];
        int2 es3 = g_es[p + 3];

        float4 v0 = *(const float4*)&g_v[(size_t)es0.y * HID + 4 * l];
        float4 v1 = *(const float4*)&g_v[(size_t)es1.y * HID + 4 * l];
        float4 v2 = *(const float4*)&g_v[(size_t)es2.y * HID + 4 * l];
        float4 v3 = *(const float4*)&g_v[(size_t)es3.y * HID + 4 * l];
        float a0 = g_alpha[(size_t)es0.x * 8 + h];
        float a1 = g_alpha[(size_t)es1.x * 8 + h];
        float a2 = g_alpha[(size_t)es2.x * 8 + h];
        float a3 = g_alpha[(size_t)es3.x * 8 + h];

        acc.x = fmaf(a0, v0.x, fmaf(a1, v1.x, fmaf(a2, v2.x, fmaf(a3, v3.x, acc.x))));
        acc.y = fmaf(a0, v0.y, fmaf(a1, v1.y, fmaf(a2, v2.y, fmaf(a3, v3.y, acc.y))));
        acc.z = fmaf(a0, v0.z, fmaf(a1, v1.z, fmaf(a2, v2.z, fmaf(a3, v3.z, acc.z))));
        acc.w = fmaf(a0, v0.w, fmaf(a1, v1.w, fmaf(a2, v2.w, fmaf(a3, v3.w, acc.w))));
    }
    for (; p < e_end; p++) {
        int2 es0 = g_es[p];
        float4 v0 = *(const float4*)&g_v[(size_t)es0.y * HID + 4 * l];
        float a0 = g_alpha[(size_t)es0.x * 8 + h];
        acc.x = fmaf(a0, v0.x, acc.x);
        acc.y = fmaf(a0, v0.y, acc.y);
        acc.z = fmaf(a0, v0.z, acc.z);
        acc.w = fmaf(a0, v0.w, acc.w);
    }

    __stcs((float4*)&out[(size_t)node * HID + 4 * l], acc);
}

// ---------------------------------------------------------------------------
extern "C" void kernel_launch(void* const* d_in, const int* in_sizes, int n_in,
                              void* d_out, int out_size) {
    const float* x      = (const float*)d_in[0];
    const float* w_ij   = (const float*)d_in[1];
    const unsigned int* ei = (const unsigned int*)d_in[2];
    const float* cutoff = (const float*)d_in[3];
    const float* Wq     = (const float*)d_in[4];
    const float* Wk     = (const float*)d_in[5];
    const float* Wv     = (const float*)d_in[6];
    float* out = (float*)d_out;

    static cudaStream_t s2 = nullptr;
    static cudaEvent_t evFork = nullptr, evSort = nullptr, evQK = nullptr, evV = nullptr;
    static bool use_streams = false;
    if (!s2 && !evFork) {
        bool ok = (cudaStreamCreateWithFlags(&s2, cudaStreamNonBlocking) == cudaSuccess)
               && (cudaEventCreateWithFlags(&evFork, cudaEventDisableTiming) == cudaSuccess)
               && (cudaEventCreateWithFlags(&evSort, cudaEventDisableTiming) == cudaSuccess)
               && (cudaEventCreateWithFlags(&evQK, cudaEventDisableTiming) == cudaSuccess)
               && (cudaEventCreateWithFlags(&evV, cudaEventDisableTiming) == cudaSuccess);
        use_streams = ok;
    }

    int gx = (NN + TILE_N - 1) / TILE_N;
    int alpha_blocks = ((NE / 2) * 32 + 255) / 256;    // warp per 2 edges
    int agg_blocks   = (NN * 32 + 255) / 256;          // warp per node

    if (use_streams) {
        cudaEventRecord(evFork, 0);
        cudaStreamWaitEvent(s2, evFork, 0);

        // s2: sort chain (independent of GEMM chain)
        zero_and_detect<<<148, 256, 0, s2>>>(ei);
        convert_idx<<<148, 256, 0, s2>>>(ei);
        scan_phase1<<<NBLK, SCAN_B, 0, s2>>>();
        scan_phase2<<<1, 64, 0, s2>>>();
        scan_phase3<<<NBLK, SCAN_B, 0, s2>>>();
        permute_idx<<<148, 256, 0, s2>>>();
        cudaEventRecord(evSort, s2);

        // main: transpose -> gemm(q,k)
        transpose_w<<<48, 256>>>(Wq, Wk, Wv);
        dim3 gqk(gx, 2);
        qkv_gemm<<<gqk, 256>>>(x, 0);
        cudaEventRecord(evQK, 0);

        // s2: gemm(v) runs concurrently with alpha_kernel on main
        cudaStreamWaitEvent(s2, evQK, 0);
        dim3 gv(gx, 1);
        qkv_gemm<<<gv, 256, 0, s2>>>(x, 2);
        cudaEventRecord(evV, s2);

        // main: alpha (needs only q,k — ordered after gemm_qk in-stream)
        alpha_kernel<<<alpha_blocks, 256>>>(w_ij, cutoff);

        // join: aggregation needs sort + v + alpha
        cudaStreamWaitEvent(0, evSort, 0);
        cudaStreamWaitEvent(0, evV, 0);
        edge_agg<<<agg_blocks, 256>>>(out);
    } else {
        zero_and_detect<<<148, 256>>>(ei);
        convert_idx<<<148, 256>>>(ei);
        scan_phase1<<<NBLK, SCAN_B>>>();
        scan_phase2<<<1, 64>>>();
        scan_phase3<<<NBLK, SCAN_B>>>();
        permute_idx<<<148, 256>>>();
        transpose_w<<<48, 256>>>(Wq, Wk, Wv);
        dim3 g3(gx, 3);
        qkv_gemm<<<g3, 256>>>(x, 0);
        alpha_kernel<<<alpha_blocks, 256>>>(w_ij, cutoff);
        edge_agg<<<agg_blocks, 256>>>(out);
    }
}

// round 9
// speedup vs baseline: 1.4014x; 1.0160x over previous
#include <cuda_runtime.h>

#define NN 50000
#define NE 600000
#define HID 128
#define TILE_N 64
#define KCH 32
#define SCAN_B 1024
#define NBLK ((NN + SCAN_B - 1) / SCAN_B)   // 49 scan blocks

typedef unsigned long long u64;

// Scratch (static device globals — no runtime allocation).
__device__ __align__(256) float g_q[(size_t)NN * HID];
__device__ __align__(256) float g_k[(size_t)NN * HID];
__device__ __align__(256) float g_v[(size_t)NN * HID];
__device__ __align__(256) float g_alpha[(size_t)NE * 8];  // per-edge per-head alpha
__device__ __align__(256) float g_WT[3 * HID * HID];
__device__ __align__(256) int   g_src[NE];
__device__ __align__(256) int   g_dst[NE];
__device__ __align__(256) int   g_count[NN];
__device__ __align__(256) int   g_start[NN + 1];
__device__ __align__(256) int   g_cursor[NN];
__device__ __align__(256) int2  g_es[NE];        // (edge id, src) sorted by dst
__device__ __align__(256) int   g_bsum[NBLK];
__device__ __align__(256) int   g_boff[NBLK];
__device__ int g_is_i32;

// ---------------------------------------------------------------------------
// f32x2 packed-FMA helpers (FFMA2 — PTX-only, exact fp32).
// ---------------------------------------------------------------------------
__device__ __forceinline__ u64 pack2(float lo, float hi) {
    u64 r; asm("mov.b64 %0, {%1, %2};" : "=l"(r) : "f"(lo), "f"(hi)); return r;
}
__device__ __forceinline__ void fma2(u64& acc, u64 a, u64 b) {
    asm("fma.rn.f32x2 %0, %1, %2, %0;" : "+l"(acc) : "l"(a), "l"(b));
}

// ---------------------------------------------------------------------------
// Kernel Z: zero counters + dtype flag + detection in one pass.
// ---------------------------------------------------------------------------
__global__ void zero_and_detect(const unsigned int* __restrict__ ei_words) {
    int t = blockIdx.x * blockDim.x + threadIdx.x;
    if (t == 0) g_is_i32 = 0;
    for (int i = t; i < NN; i += blockDim.x * gridDim.x) g_count[i] = 0;
    unsigned int acc = 0;
    for (int i = t; i < NE; i += blockDim.x * gridDim.x)
        acc |= ei_words[2 * i + 1];
    if (acc) atomicOr(&g_is_i32, 1);
}

// ---------------------------------------------------------------------------
// Kernel B: decode edge_index into g_src/g_dst AND histogram dst degrees.
// ---------------------------------------------------------------------------
__global__ void convert_idx(const unsigned int* __restrict__ ei_words) {
    int t = blockIdx.x * blockDim.x + threadIdx.x;
    int i32 = g_is_i32;
    for (int e = t; e < NE; e += blockDim.x * gridDim.x) {
        int s, d;
        if (i32) {
            s = (int)ei_words[e];
            d = (int)ei_words[NE + e];
        } else {
            s = (int)ei_words[2 * (size_t)e];
            d = (int)ei_words[2 * ((size_t)NE + e)];
        }
        g_src[e] = s;
        g_dst[e] = d;
        atomicAdd(&g_count[d], 1);
    }
}

// ---------------------------------------------------------------------------
// 3-phase parallel scan.
// ---------------------------------------------------------------------------
__global__ __launch_bounds__(SCAN_B) void scan_phase1() {
    __shared__ int ps[SCAN_B];
    int tid = threadIdx.x;
    int idx = blockIdx.x * SCAN_B + tid;
    int val = (idx < NN) ? g_count[idx] : 0;
    ps[tid] = val;
    __syncthreads();
#pragma unroll
    for (int d = 1; d < SCAN_B; d <<= 1) {
        int v = (tid >= d) ? ps[tid - d] : 0;
        __syncthreads();
        ps[tid] += v;
        __syncthreads();
    }
    if (idx < NN) g_start[idx] = ps[tid] - val;
    if (tid == SCAN_B - 1) g_bsum[blockIdx.x] = ps[tid];
}

__global__ void scan_phase2() {
    int l = threadIdx.x;             // 64 threads, NBLK=49 <= 64
    int v = (l < NBLK) ? g_bsum[l] : 0;
    int orig = v;
    __shared__ int s[64];
    s[l] = v;
    __syncthreads();
#pragma unroll
    for (int d = 1; d < 64; d <<= 1) {
        int t = (l >= d) ? s[l - d] : 0;
        __syncthreads();
        s[l] += t;
        __syncthreads();
    }
    if (l < NBLK) g_boff[l] = s[l] - orig;
    if (l == 63) g_start[NN] = s[63];
}

__global__ __launch_bounds__(SCAN_B) void scan_phase3() {
    int idx = blockIdx.x * SCAN_B + threadIdx.x;
    if (idx < NN) {
        int v = g_start[idx] + g_boff[blockIdx.x];
        g_start[idx] = v;
        g_cursor[idx] = v;
    }
}

// ---------------------------------------------------------------------------
// Kernel D: permute (edge id, src) pairs into dst-sorted order.
// ---------------------------------------------------------------------------
__global__ void permute_idx() {
    int t = blockIdx.x * blockDim.x + threadIdx.x;
    for (int e = t; e < NE; e += blockDim.x * gridDim.x) {
        int d = g_dst[e];
        int pos = atomicAdd(&g_cursor[d], 1);
        g_es[pos] = make_int2(e, g_src[e]);
    }
}

// ---------------------------------------------------------------------------
// Kernel 0: transpose the three 128x128 weight matrices (tiny).
// ---------------------------------------------------------------------------
__global__ void transpose_w(const float* __restrict__ Wq,
                            const float* __restrict__ Wk,
                            const float* __restrict__ Wv) {
    int t = blockIdx.x * blockDim.x + threadIdx.x;
    int total = 3 * HID * HID;
    for (int idx = t; idx < total; idx += blockDim.x * gridDim.x) {
        int m = idx / (HID * HID);
        int r = idx - m * (HID * HID);
        int o = r >> 7;
        int d = r & 127;
        const float* W = (m == 0) ? Wq : (m == 1) ? Wk : Wv;
        g_WT[m * HID * HID + d * HID + o] = W[o * HID + d];
    }
}

// ---------------------------------------------------------------------------
// Kernel 1: QKV GEMM (FFMA2). No register staging (proven neutral in R4,
// costs ~24 regs); __launch_bounds__(256,3) caps regs so 3 CTAs/SM fit
// (occ 24% -> 36%), more warps to cover FFMA latency chains.
// ---------------------------------------------------------------------------
__global__ __launch_bounds__(256, 3) void qkv_gemm(const float* __restrict__ x,
                                                   int m_base) {
    __shared__ float wt[KCH][HID];
    __shared__ float xs[TILE_N][KCH];

    int m = blockIdx.y + m_base;
    const float* wtg = &g_WT[m * HID * HID];
    float* out = (m == 0) ? g_q : (m == 1) ? g_k : g_v;

    int node0 = blockIdx.x * TILE_N;
    int tid = threadIdx.x;
    int w = tid >> 5;
    int l = tid & 31;

    const float4* xg4 = (const float4*)x;
    int xn0 = tid >> 3,         xc0 = tid & 7;
    int xn1 = (tid + 256) >> 3, xc1 = (tid + 256) & 7;
    int gn0 = node0 + xn0, gn1 = node0 + xn1;

    u64 cxy[8], czw[8];
#pragma unroll
    for (int n = 0; n < 8; n++) { cxy[n] = 0ull; czw[n] = 0ull; }

#pragma unroll
    for (int kk = 0; kk < HID / KCH; kk++) {
        int k0 = kk * KCH;
        if (kk) __syncthreads();
        // W chunk: 1024 float4 / 256 threads = 4 each
        {
            float4* wt4 = (float4*)&wt[0][0];
            const float4* srcw = (const float4*)&wtg[(size_t)k0 * HID];
#pragma unroll
            for (int i = 0; i < 4; i++)
                wt4[tid + i * 256] = srcw[tid + i * 256];
        }
        // x chunk: 512 float4 / 256 threads = 2 each
        {
            float4* xs4 = (float4*)&xs[0][0];
            xs4[tid] = (gn0 < NN) ? xg4[(size_t)gn0 * 32 + (k0 >> 2) + xc0]
                                  : make_float4(0.f, 0.f, 0.f, 0.f);
            xs4[tid + 256] = (gn1 < NN) ? xg4[(size_t)gn1 * 32 + (k0 >> 2) + xc1]
                                        : make_float4(0.f, 0.f, 0.f, 0.f);
        }
        __syncthreads();

#pragma unroll
        for (int d4 = 0; d4 < KCH / 4; d4++) {
            int d = d4 * 4;
            ulonglong2 w0 = *(ulonglong2*)&wt[d + 0][4 * l];
            ulonglong2 w1 = *(ulonglong2*)&wt[d + 1][4 * l];
            ulonglong2 w2 = *(ulonglong2*)&wt[d + 2][4 * l];
            ulonglong2 w3 = *(ulonglong2*)&wt[d + 3][4 * l];
#pragma unroll
            for (int n = 0; n < 8; n++) {
                float4 xv = *(float4*)&xs[8 * w + n][d];
                u64 xb0 = pack2(xv.x, xv.x);
                u64 xb1 = pack2(xv.y, xv.y);
                u64 xb2 = pack2(xv.z, xv.z);
                u64 xb3 = pack2(xv.w, xv.w);
                fma2(cxy[n], xb0, w0.x); fma2(czw[n], xb0, w0.y);
                fma2(cxy[n], xb1, w1.x); fma2(czw[n], xb1, w1.y);
                fma2(cxy[n], xb2, w2.x); fma2(czw[n], xb2, w2.y);
                fma2(cxy[n], xb3, w3.x); fma2(czw[n], xb3, w3.y);
            }
        }
    }

#pragma unroll
    for (int n = 0; n < 8; n++) {
        int gn = node0 + 8 * w + n;
        if (gn < NN) {
            ulonglong2 o2;
            o2.x = cxy[n];
            o2.y = czw[n];
            *(ulonglong2*)&out[(size_t)gn * HID + 4 * l] = o2;
        }
    }
}

// ---------------------------------------------------------------------------
// Kernel 2a: alpha in EDGE order, 4 edges per warp (8 gathers + 4 streams
// in flight). w_ij/cutoff streamed with __ldcs; quad = 1 head; writes
// alpha[e][h] with cutoff and 1/sqrt(16) folded in.
// ---------------------------------------------------------------------------
__global__ __launch_bounds__(256) void alpha_kernel(
    const float* __restrict__ w_ij,
    const float* __restrict__ cutoff) {

    int wg = (blockIdx.x * blockDim.x + threadIdx.x) >> 5;
    int l = threadIdx.x & 31;
    int e0 = wg * 4;
    if (e0 >= NE) return;   // NE % 4 == 0 -> no tail handling

    float pr[4];
#pragma unroll
    for (int j = 0; j < 4; j++) {
        int e = e0 + j;
        int s = g_src[e], d = g_dst[e];
        float4 q = *(const float4*)&g_q[(size_t)d * HID + 4 * l];
        float4 k = *(const float4*)&g_k[(size_t)s * HID + 4 * l];
        float4 wv = __ldcs((const float4*)&w_ij[(size_t)e * HID + 4 * l]);
        pr[j] = q.x * wv.x * k.x + q.y * wv.y * k.y +
                q.z * wv.z * k.z + q.w * wv.w * k.w;
    }
#pragma unroll
    for (int j = 0; j < 4; j++) {
        pr[j] += __shfl_xor_sync(0xffffffffu, pr[j], 1);
        pr[j] += __shfl_xor_sync(0xffffffffu, pr[j], 2);
    }
    if ((l & 3) == 0) {
        int h = l >> 2;
#pragma unroll
        for (int j = 0; j < 4; j++) {
            float c = __ldcs(&cutoff[e0 + j]);
            g_alpha[(size_t)(e0 + j) * 8 + h] = pr[j] * 0.25f * c;
        }
    }
}

// ---------------------------------------------------------------------------
// Kernel 2b: dst-sorted aggregation. One warp per node; per edge a v-gather
// (L2-resident) + 32B alpha gather. Unroll 4. No atomics.
// ---------------------------------------------------------------------------
__global__ __launch_bounds__(256) void edge_agg(float* __restrict__ out) {
    int node = (blockIdx.x * blockDim.x + threadIdx.x) >> 5;
    int l = threadIdx.x & 31;
    if (node >= NN) return;

    int p     = g_start[node];
    int e_end = g_start[node + 1];
    int h = l >> 2;

    float4 acc = make_float4(0.f, 0.f, 0.f, 0.f);

    for (; p + 4 <= e_end; p += 4) {
        int2 es0 = g_es[p];
        int2 es1 = g_es[p + 1];
        int2 es2 = g_es[p + 2];
        int2 es3 = g_es[p + 3];

        float4 v0 = *(const float4*)&g_v[(size_t)es0.y * HID + 4 * l];
        float4 v1 = *(const float4*)&g_v[(size_t)es1.y * HID + 4 * l];
        float4 v2 = *(const float4*)&g_v[(size_t)es2.y * HID + 4 * l];
        float4 v3 = *(const float4*)&g_v[(size_t)es3.y * HID + 4 * l];
        float a0 = g_alpha[(size_t)es0.x * 8 + h];
        float a1 = g_alpha[(size_t)es1.x * 8 + h];
        float a2 = g_alpha[(size_t)es2.x * 8 + h];
        float a3 = g_alpha[(size_t)es3.x * 8 + h];

        acc.x = fmaf(a0, v0.x, fmaf(a1, v1.x, fmaf(a2, v2.x, fmaf(a3, v3.x, acc.x))));
        acc.y = fmaf(a0, v0.y, fmaf(a1, v1.y, fmaf(a2, v2.y, fmaf(a3, v3.y, acc.y))));
        acc.z = fmaf(a0, v0.z, fmaf(a1, v1.z, fmaf(a2, v2.z, fmaf(a3, v3.z, acc.z))));
        acc.w = fmaf(a0, v0.w, fmaf(a1, v1.w, fmaf(a2, v2.w, fmaf(a3, v3.w, acc.w))));
    }
    for (; p < e_end; p++) {
        int2 es0 = g_es[p];
        float4 v0 = *(const float4*)&g_v[(size_t)es0.y * HID + 4 * l];
        float a0 = g_alpha[(size_t)es0.x * 8 + h];
        acc.x = fmaf(a0, v0.x, acc.x);
        acc.y = fmaf(a0, v0.y, acc.y);
        acc.z = fmaf(a0, v0.z, acc.z);
        acc.w = fmaf(a0, v0.w, acc.w);
    }

    __stcs((float4*)&out[(size_t)node * HID + 4 * l], acc);
}

// ---------------------------------------------------------------------------
extern "C" void kernel_launch(void* const* d_in, const int* in_sizes, int n_in,
                              void* d_out, int out_size) {
    const float* x      = (const float*)d_in[0];
    const float* w_ij   = (const float*)d_in[1];
    const unsigned int* ei = (const unsigned int*)d_in[2];
    const float* cutoff = (const float*)d_in[3];
    const float* Wq     = (const float*)d_in[4];
    const float* Wk     = (const float*)d_in[5];
    const float* Wv     = (const float*)d_in[6];
    float* out = (float*)d_out;

    static cudaStream_t s2 = nullptr;
    static cudaEvent_t evFork = nullptr, evSort = nullptr, evQK = nullptr, evV = nullptr;
    static bool use_streams = false;
    if (!s2 && !evFork) {
        bool ok = (cudaStreamCreateWithFlags(&s2, cudaStreamNonBlocking) == cudaSuccess)
               && (cudaEventCreateWithFlags(&evFork, cudaEventDisableTiming) == cudaSuccess)
               && (cudaEventCreateWithFlags(&evSort, cudaEventDisableTiming) == cudaSuccess)
               && (cudaEventCreateWithFlags(&evQK, cudaEventDisableTiming) == cudaSuccess)
               && (cudaEventCreateWithFlags(&evV, cudaEventDisableTiming) == cudaSuccess);
        use_streams = ok;
    }

    int gx = (NN + TILE_N - 1) / TILE_N;
    int alpha_blocks = ((NE / 4) * 32 + 255) / 256;    // warp per 4 edges
    int agg_blocks   = (NN * 32 + 255) / 256;          // warp per node

    if (use_streams) {
        cudaEventRecord(evFork, 0);
        cudaStreamWaitEvent(s2, evFork, 0);

        // s2: sort chain (independent of GEMM chain)
        zero_and_detect<<<148, 256, 0, s2>>>(ei);
        convert_idx<<<148, 256, 0, s2>>>(ei);
        scan_phase1<<<NBLK, SCAN_B, 0, s2>>>();
        scan_phase2<<<1, 64, 0, s2>>>();
        scan_phase3<<<NBLK, SCAN_B, 0, s2>>>();
        permute_idx<<<148, 256, 0, s2>>>();
        cudaEventRecord(evSort, s2);

        // main: transpose -> gemm(q,k)
        transpose_w<<<48, 256>>>(Wq, Wk, Wv);
        dim3 gqk(gx, 2);
        qkv_gemm<<<gqk, 256>>>(x, 0);
        cudaEventRecord(evQK, 0);

        // s2: gemm(v) runs concurrently with alpha_kernel on main
        cudaStreamWaitEvent(s2, evQK, 0);
        dim3 gv(gx, 1);
        qkv_gemm<<<gv, 256, 0, s2>>>(x, 2);
        cudaEventRecord(evV, s2);

        // main: alpha (needs only q,k — ordered after gemm_qk in-stream)
        alpha_kernel<<<alpha_blocks, 256>>>(w_ij, cutoff);

        // join: aggregation needs sort + v + alpha
        cudaStreamWaitEvent(0, evSort, 0);
        cudaStreamWaitEvent(0, evV, 0);
        edge_agg<<<agg_blocks, 256>>>(out);
    } else {
        zero_and_detect<<<148, 256>>>(ei);
        convert_idx<<<148, 256>>>(ei);
        scan_phase1<<<NBLK, SCAN_B>>>();
        scan_phase2<<<1, 64>>>();
        scan_phase3<<<NBLK, SCAN_B>>>();
        permute_idx<<<148, 256>>>();
        transpose_w<<<48, 256>>>(Wq, Wk, Wv);
        dim3 g3(gx, 3);
        qkv_gemm<<<g3, 256>>>(x, 0);
        alpha_kernel<<<alpha_blocks, 256>>>(w_ij, cutoff);
        edge_agg<<<agg_blocks, 256>>>(out);
    }
}